// round 6
// baseline (speedup 1.0000x reference)
#include <cuda_runtime.h>

typedef unsigned long long u64;
typedef unsigned int u32;

#define B_TOT   256
#define IN_CAPS 1152
#define KDIM    8
#define NCAPS   10
#define DDIM    16
#define CHUNKS  72
#define I_PER   16
#define BGROUPS 8
#define SND     (B_TOT*NCAPS*DDIM)      /* 40960 */
#define FDIM    (IN_CAPS*KDIM)          /* 9216  */
#define XBLKS   ((FDIM/32)*(B_TOT/32))  /* 2304  */
#define WELEMS  (NCAPS*IN_CAPS*128)     /* 1474560 */
#define WBLKS   ((WELEMS+1023)/1024)    /* 1440  */

// ---------------- scratch (static device memory, no allocs) ----------------
__device__ float g_Wt[NCAPS*IN_CAPS*128];        // W transposed: [n][i][k][d]
__device__ float g_xT[FDIM*B_TOT];               // x transposed: [i*8+k][b]
__device__ float g_spart[CHUNKS*SND];            // per-chunk partial s
__device__ float g_vc[SND];                      // CUMULATIVE v  [b][n][d]

// ---------------- f32x2 helpers ----------------
__device__ __forceinline__ u64 pk2(float x, float y){
    u64 r; asm("mov.b64 %0,{%1,%2};" : "=l"(r) : "f"(x), "f"(y)); return r;
}
__device__ __forceinline__ void upk2(u64 a, float& x, float& y){
    asm("mov.b64 {%0,%1},%2;" : "=f"(x), "=f"(y) : "l"(a));
}
__device__ __forceinline__ u64 ffma2(u64 a, u64 b, u64 c){
    u64 d; asm("fma.rn.f32x2 %0,%1,%2,%3;" : "=l"(d) : "l"(a), "l"(b), "l"(c)); return d;
}
__device__ __forceinline__ u64 fmul2(u64 a, u64 b){
    u64 d; asm("mul.rn.f32x2 %0,%1,%2;" : "=l"(d) : "l"(a), "l"(b)); return d;
}
__device__ __forceinline__ u64 fadd2(u64 a, u64 b){
    u64 d; asm("add.rn.f32x2 %0,%1,%2;" : "=l"(d) : "l"(a), "l"(b)); return d;
}
__device__ __forceinline__ u32 smemu32(const void* p){
    u32 a; asm("{ .reg .u64 t; cvta.to.shared.u64 t, %1; cvt.u32.u64 %0, t; }" : "=r"(a) : "l"(p));
    return a;
}
__device__ __forceinline__ void cpasync16(u32 dst, const void* src){
    asm volatile("cp.async.ca.shared.global [%0],[%1],16;" :: "r"(dst), "l"(src));
}
__device__ __forceinline__ void cpcommit(){ asm volatile("cp.async.commit_group;"); }
__device__ __forceinline__ void cpwait1(){ asm volatile("cp.async.wait_group 1;"); }

// tu[d-pairs] = sum_k Wt[k][:] * x_k  (warp-uniform broadcast LDS + f32x2 FMA)
__device__ __forceinline__ void tu_compute(const ulonglong2* __restrict__ wrow,
                                           const float* __restrict__ X, u64* a){
    #pragma unroll
    for (int k = 0; k < 8; k++){
        u64 xk = pk2(X[k], X[k]);
        #pragma unroll
        for (int q = 0; q < 4; q++){
            ulonglong2 w = wrow[k*4 + q];
            if (k == 0){
                a[2*q]   = fmul2(w.x, xk); a[2*q+1] = fmul2(w.y, xk);
            } else {
                a[2*q]   = ffma2(w.x, xk, a[2*q]);
                a[2*q+1] = ffma2(w.y, xk, a[2*q+1]);
            }
        }
    }
}

// ---------------- prep: both transposes in ONE kernel ----------------
__global__ void k_prep(const float* __restrict__ x, const float* __restrict__ W){
    __shared__ float t[32][33];
    int xb = blockIdx.x;
    int tid = threadIdx.x;
    if (xb < XBLKS){
        int tx = tid & 31, ty = tid >> 5;
        int f0 = (xb % (FDIM/32)) * 32;
        int b0 = (xb / (FDIM/32)) * 32;
        t[ty][tx] = x[(size_t)(b0 + ty) * FDIM + f0 + tx];
        __syncthreads();
        g_xT[(size_t)(f0 + ty) * B_TOT + b0 + tx] = t[tx][ty];
    } else {
        int idx = (xb - XBLKS) * 1024 + tid;
        if (idx < WELEMS){
            int k  = idx & 7;
            int d  = (idx >> 3) & 15;
            int ni = idx >> 7;
            g_Wt[(ni << 7) | (k << 4) | d] = W[idx];
        }
    }
}

// ---------------- main pass kernel ----------------
// warp = capsule n (10 warps), lane = batch. grid = (72 chunks, 8 bgroups) = 576 CTAs,
// 3 CTAs/SM. ROUTE=0: uniform c, zero barriers. ROUTE=1: logit = tu . vc (cumulative v),
// one barrier per i-step, ping-pong exchange.
template<int ROUTE>
__global__ void __launch_bounds__(320, 3) k_pass(){
    __shared__ __align__(16) float ws[2][NCAPS*128];   // double-buffered W tile
    __shared__ float ex[2][NCAPS][32];                 // ping-pong exp exchange

    const int tid   = threadIdx.x;
    const int n     = tid >> 5;
    const int lane  = tid & 31;
    const int chunk = blockIdx.x;
    const int bg    = blockIdx.y;
    const int i0    = chunk * I_PER;
    const int b     = bg * 32 + lane;

    u64 v[8];
    if (ROUTE){
        const u64* vp = (const u64*)&g_vc[(b*NCAPS + n)*DDIM];
        #pragma unroll
        for (int p = 0; p < 8; p++) v[p] = vp[p];
    }
    u64 s[8];
    #pragma unroll
    for (int p = 0; p < 8; p++) s[p] = 0ull;

    const float* wsrc = g_Wt + ((size_t)(n*IN_CAPS + i0))*128 + lane*4;
    const u32 wdst0 = smemu32(&ws[0][n*128 + lane*4]);
    const u32 wdst1 = smemu32(&ws[1][n*128 + lane*4]);
    const float* xp = g_xT + (size_t)i0 * KDIM * B_TOT + b;

    cpasync16(wdst0, wsrc);            // stage ii = 0
    cpcommit();

    #pragma unroll 1
    for (int ii = 0; ii < I_PER; ii++){
        if (ii + 1 < I_PER) cpasync16((ii & 1) ? wdst0 : wdst1, wsrc + 128);
        cpcommit();
        wsrc += 128;
        cpwait1();                      // current buffer ready

        float X[8];
        #pragma unroll
        for (int k = 0; k < 8; k++) X[k] = xp[k * B_TOT];   // coalesced, L1-shared
        xp += KDIM * B_TOT;

        u64 a[8];
        tu_compute((const ulonglong2*)&ws[ii & 1][n*128], X, a);

        if (!ROUTE){
            #pragma unroll
            for (int p = 0; p < 8; p++) s[p] = fadd2(s[p], a[p]);
        } else {
            u64 d0 = fmul2(a[0], v[0]);
            #pragma unroll
            for (int p = 1; p < 8; p++) d0 = ffma2(a[p], v[p], d0);
            float lo, hi; upk2(d0, lo, hi);
            float e = __expf(lo + hi);      // |logit| small: no max-sub needed
            ex[ii & 1][n][lane] = e;
            __syncthreads();                // one barrier per i-step
            float Z = ex[ii & 1][0][lane];  // conflict-free column reads
            #pragma unroll
            for (int j = 1; j < NCAPS; j++) Z += ex[ii & 1][j][lane];
            float c = __fdividef(e, Z);
            u64 cc = pk2(c, c);
            #pragma unroll
            for (int p = 0; p < 8; p++) s[p] = ffma2(a[p], cc, s[p]);
        }
    }

    // deterministic per-chunk partials (no atomics)
    float* sp = g_spart + ((size_t)(chunk*B_TOT + b)*NCAPS + n)*DDIM;
    #pragma unroll
    for (int q = 0; q < 4; q++)
        ((ulonglong2*)sp)[q] = make_ulonglong2(s[2*q], s[2*q+1]);
}

// ---------------- reduce partials + squash (4 warps per (b,n), 72 chunks) ----
// MODE 0: vc = v ; MODE 1: vc += v ; MODE 2: out = v
template<int MODE>
__global__ void k_reduce(float* __restrict__ out, float scale){
    __shared__ float red[2][4][16];
    const int tid  = threadIdx.x;
    const int wid  = tid >> 5;            // 0..7
    const int lane = tid & 31;
    const int pib  = wid >> 2;            // pair-in-block 0..1
    const int q    = wid & 3;             // quarter 0..3
    const int pair = blockIdx.x * 2 + pib;      // (b,n) in [0, 2560)
    const int d    = lane & 15;
    const int hh   = lane >> 4;
    const size_t base = (size_t)pair * DDIM + d;

    float s = 0.f;
    #pragma unroll
    for (int j = 0; j < 9; j++)
        s += g_spart[(size_t)(2*q + hh + 8*j) * SND + base];
    s += __shfl_xor_sync(0xffffffffu, s, 16);
    if (lane < 16) red[pib][q][d] = s;
    __syncthreads();
    if (q == 0){
        float st = (red[pib][0][d] + red[pib][1][d] + red[pib][2][d] + red[pib][3][d]) * scale;
        float sq = st * st;
        sq += __shfl_xor_sync(0xffffffffu, sq, 1);
        sq += __shfl_xor_sync(0xffffffffu, sq, 2);
        sq += __shfl_xor_sync(0xffffffffu, sq, 4);
        sq += __shfl_xor_sync(0xffffffffu, sq, 8);
        float nrm = sqrtf(sq);
        float vv = (sq / (1.0f + sq)) * (st / (nrm + 1e-8f));
        if (lane < 16){
            if (MODE == 0)      g_vc[base] = vv;
            else if (MODE == 1) g_vc[base] += vv;
            else                out[base] = vv;
        }
    }
}

// ---------------- launch ----------------
extern "C" void kernel_launch(void* const* d_in, const int* in_sizes, int n_in,
                              void* d_out, int out_size){
    const float* x = (const float*)d_in[0];
    const float* W = (const float*)d_in[1];
    if (n_in >= 2 && in_sizes[0] == WELEMS){   // defensive order swap
        const float* t = x; x = W; W = t;
    }
    float* out = (float*)d_out;

    k_prep<<<XBLKS + WBLKS, 1024>>>(x, W);

    dim3 pg(CHUNKS, BGROUPS);
    const int RB = (B_TOT*NCAPS)/2;    // 1280 blocks

    k_pass<0><<<pg, 320>>>();
    k_reduce<0><<<RB, 256>>>(nullptr, 0.1f);   // c = softmax(0) = 1/10

    k_pass<1><<<pg, 320>>>();
    k_reduce<1><<<RB, 256>>>(nullptr, 1.0f);

    k_pass<1><<<pg, 320>>>();
    k_reduce<1><<<RB, 256>>>(nullptr, 1.0f);

    k_pass<1><<<pg, 320>>>();
    k_reduce<2><<<RB, 256>>>(out, 1.0f);
}

// round 7
// speedup vs baseline: 1.3116x; 1.3116x over previous
#include <cuda_runtime.h>

typedef unsigned long long u64;
typedef unsigned int u32;

#define B_TOT   256
#define IN_CAPS 1152
#define KDIM    8
#define NCAPS   10
#define DDIM    16
#define CHUNKS  36
#define I_PER   32
#define BGROUPS 8
#define SND     (B_TOT*NCAPS*DDIM)      /* 40960 */
#define FDIM    (IN_CAPS*KDIM)          /* 9216  */
#define XBLKS   ((FDIM/32)*(B_TOT/32))  /* 2304  */
#define WELEMS  (NCAPS*IN_CAPS*128)     /* 1474560 */
#define WBLKS   ((WELEMS+1023)/1024)    /* 1440  */

// ---------------- scratch (static device memory, no allocs) ----------------
__device__ float g_Wt[NCAPS*IN_CAPS*128];        // W transposed: [n][i][k][d]
__device__ float g_xT[FDIM*B_TOT];               // x transposed: [i*8+k][b]
__device__ float g_spart[CHUNKS*SND];            // per-chunk partial s
__device__ float g_vc[SND];                      // CUMULATIVE v  [b][n][d]

// ---------------- f32x2 helpers ----------------
__device__ __forceinline__ u64 pk2(float x, float y){
    u64 r; asm("mov.b64 %0,{%1,%2};" : "=l"(r) : "f"(x), "f"(y)); return r;
}
__device__ __forceinline__ void upk2(u64 a, float& x, float& y){
    asm("mov.b64 {%0,%1},%2;" : "=f"(x), "=f"(y) : "l"(a));
}
__device__ __forceinline__ u64 ffma2(u64 a, u64 b, u64 c){
    u64 d; asm("fma.rn.f32x2 %0,%1,%2,%3;" : "=l"(d) : "l"(a), "l"(b), "l"(c)); return d;
}
__device__ __forceinline__ u64 fmul2(u64 a, u64 b){
    u64 d; asm("mul.rn.f32x2 %0,%1,%2;" : "=l"(d) : "l"(a), "l"(b)); return d;
}
__device__ __forceinline__ u64 fadd2(u64 a, u64 b){
    u64 d; asm("add.rn.f32x2 %0,%1,%2;" : "=l"(d) : "l"(a), "l"(b)); return d;
}
__device__ __forceinline__ u32 smemu32(const void* p){
    u32 a; asm("{ .reg .u64 t; cvta.to.shared.u64 t, %1; cvt.u32.u64 %0, t; }" : "=r"(a) : "l"(p));
    return a;
}
__device__ __forceinline__ void cpasync16(u32 dst, const void* src){
    asm volatile("cp.async.ca.shared.global [%0],[%1],16;" :: "r"(dst), "l"(src));
}
__device__ __forceinline__ void cpcommit(){ asm volatile("cp.async.commit_group;"); }
__device__ __forceinline__ void cpwait1(){ asm volatile("cp.async.wait_group 1;"); }

// tu[d-pairs] = sum_k Wt[k][:] * x_k  (warp-uniform broadcast LDS + f32x2 FMA)
__device__ __forceinline__ void tu_compute(const ulonglong2* __restrict__ wrow,
                                           const float* __restrict__ X, u64* a){
    #pragma unroll
    for (int k = 0; k < 8; k++){
        u64 xk = pk2(X[k], X[k]);
        #pragma unroll
        for (int q = 0; q < 4; q++){
            ulonglong2 w = wrow[k*4 + q];
            if (k == 0){
                a[2*q]   = fmul2(w.x, xk); a[2*q+1] = fmul2(w.y, xk);
            } else {
                a[2*q]   = ffma2(w.x, xk, a[2*q]);
                a[2*q+1] = ffma2(w.y, xk, a[2*q+1]);
            }
        }
    }
}

// ---------------- prep: both transposes in ONE kernel ----------------
__global__ void k_prep(const float* __restrict__ x, const float* __restrict__ W){
    __shared__ float t[32][33];
    int xb = blockIdx.x;
    int tid = threadIdx.x;
    if (xb < XBLKS){
        int tx = tid & 31, ty = tid >> 5;
        int f0 = (xb % (FDIM/32)) * 32;
        int b0 = (xb / (FDIM/32)) * 32;
        t[ty][tx] = x[(size_t)(b0 + ty) * FDIM + f0 + tx];
        __syncthreads();
        g_xT[(size_t)(f0 + ty) * B_TOT + b0 + tx] = t[tx][ty];
    } else {
        int idx = (xb - XBLKS) * 1024 + tid;
        if (idx < WELEMS){
            int k  = idx & 7;
            int d  = (idx >> 3) & 15;
            int ni = idx >> 7;
            g_Wt[(ni << 7) | (k << 4) | d] = W[idx];
        }
    }
}

// ---------------- main pass kernel ----------------
// warp = capsule n (10 warps), lane = batch. grid = (36 chunks, 8 bgroups), 2 CTAs/SM.
// ROUTE=0: c uniform -> pure accumulation, zero barriers.
// ROUTE=1: logit = tu . vc (cumulative v). Two i-steps per barrier PAIR; softmax
//          denominators computed once by reducer warps 0/1 (not replicated x10).
template<int ROUTE>
__global__ void __launch_bounds__(320, 2) k_pass(){
    __shared__ __align__(16) float ws[2][NCAPS*128];   // W slots: even-i / odd-i
    __shared__ float ex[4][NCAPS][32];                 // 4-way ping-pong exp exchange
    __shared__ float zi[4][32];                        // 1/Z per batch, per buffer

    const int tid   = threadIdx.x;
    const int n     = tid >> 5;
    const int lane  = tid & 31;
    const int chunk = blockIdx.x;
    const int bg    = blockIdx.y;
    const int i0    = chunk * I_PER;
    const int b     = bg * 32 + lane;

    u64 v[8];
    if (ROUTE){
        const u64* vp = (const u64*)&g_vc[(b*NCAPS + n)*DDIM];
        #pragma unroll
        for (int p = 0; p < 8; p++) v[p] = vp[p];
    }
    u64 s[8];
    #pragma unroll
    for (int p = 0; p < 8; p++) s[p] = 0ull;

    const float* wsrc = g_Wt + ((size_t)(n*IN_CAPS + i0))*128 + lane*4;
    const u32 wdst0 = smemu32(&ws[0][n*128 + lane*4]);
    const u32 wdst1 = smemu32(&ws[1][n*128 + lane*4]);
    const float* xp = g_xT + (size_t)i0 * KDIM * B_TOT + b;

    if (!ROUTE){
        // -------- iteration 0: no routing, no barriers --------
        cpasync16(wdst0, wsrc); cpcommit();
        #pragma unroll 1
        for (int ii = 0; ii < I_PER; ii++){
            if (ii + 1 < I_PER) cpasync16((ii & 1) ? wdst0 : wdst1, wsrc + 128);
            cpcommit();
            wsrc += 128;
            cpwait1();
            float X[8];
            #pragma unroll
            for (int k = 0; k < 8; k++) X[k] = xp[k * B_TOT];
            xp += KDIM * B_TOT;
            u64 a[8];
            tu_compute((const ulonglong2*)&ws[ii & 1][n*128], X, a);
            #pragma unroll
            for (int p = 0; p < 8; p++) s[p] = fadd2(s[p], a[p]);
        }
    } else {
        // -------- routed iterations: 2 i-steps per barrier pair --------
        cpasync16(wdst0, wsrc);        cpcommit();   // W(i0+0)
        cpasync16(wdst1, wsrc + 128);  cpcommit();   // W(i0+1)
        #pragma unroll 1
        for (int ii = 0; ii < I_PER; ii += 2){
            const int bufA = ((ii >> 1) & 1) * 2;

            // ---- sub-step A (even i, slot0) ----
            cpwait1();                              // W(ii) ready
            float XA[8];
            #pragma unroll
            for (int k = 0; k < 8; k++) XA[k] = xp[k * B_TOT];
            u64 aA[8];
            tu_compute((const ulonglong2*)&ws[0][n*128], XA, aA);
            u64 dA = fmul2(aA[0], v[0]);
            #pragma unroll
            for (int p = 1; p < 8; p++) dA = ffma2(aA[p], v[p], dA);
            float lA, hA; upk2(dA, lA, hA);
            float eA = __expf(lA + hA);             // |logit| small: no max-sub needed
            ex[bufA][n][lane] = eA;
            if (ii + 2 < I_PER) cpasync16(wdst0, wsrc + 256);   // W(ii+2)
            cpcommit();

            // ---- sub-step B (odd i, slot1) ----
            cpwait1();                              // W(ii+1) ready
            float XB[8];
            #pragma unroll
            for (int k = 0; k < 8; k++) XB[k] = xp[(8 + k) * B_TOT];
            xp += 2 * KDIM * B_TOT;
            u64 aB[8];
            tu_compute((const ulonglong2*)&ws[1][n*128], XB, aB);
            u64 dB = fmul2(aB[0], v[0]);
            #pragma unroll
            for (int p = 1; p < 8; p++) dB = ffma2(aB[p], v[p], dB);
            float lB, hB; upk2(dB, lB, hB);
            float eB = __expf(lB + hB);
            ex[bufA + 1][n][lane] = eB;
            if (ii + 3 < I_PER) cpasync16(wdst1, wsrc + 384);   // W(ii+3)
            cpcommit();
            wsrc += 256;

            __syncthreads();                        // all e's visible

            // reducer warps: warp0 -> A, warp1 -> B (one RCP per lane, not per thread)
            if (n < 2){
                const int buf = bufA + n;
                float Z = ex[buf][0][lane];
                #pragma unroll
                for (int j = 1; j < NCAPS; j++) Z += ex[buf][j][lane];
                zi[buf][lane] = __fdividef(1.0f, Z);
            }
            __syncthreads();                        // invZ visible

            float cA = eA * zi[bufA][lane];
            float cB = eB * zi[bufA + 1][lane];
            u64 ccA = pk2(cA, cA), ccB = pk2(cB, cB);
            #pragma unroll
            for (int p = 0; p < 8; p++){
                s[p] = ffma2(aA[p], ccA, s[p]);
                s[p] = ffma2(aB[p], ccB, s[p]);
            }
        }
    }

    // deterministic per-chunk partials (no atomics)
    float* sp = g_spart + ((size_t)(chunk*B_TOT + b)*NCAPS + n)*DDIM;
    #pragma unroll
    for (int q = 0; q < 4; q++)
        ((ulonglong2*)sp)[q] = make_ulonglong2(s[2*q], s[2*q+1]);
}

// ---------------- reduce partials + squash (2 warps per (b,n)) ----------------
// MODE 0: vc = v ; MODE 1: vc += v ; MODE 2: out = v
template<int MODE>
__global__ void k_reduce(float* __restrict__ out, float scale){
    __shared__ float red[4][2][16];
    const int tid  = threadIdx.x;
    const int wid  = tid >> 5;           // 0..7
    const int lane = tid & 31;
    const int pib  = wid >> 1;           // pair-in-block 0..3
    const int half = wid & 1;
    const int pair = blockIdx.x * 4 + pib;     // (b,n) in [0, 2560)
    const int d    = lane & 15;
    const int hh   = lane >> 4;
    const size_t base = (size_t)pair * DDIM + d;

    float s = 0.f;
    #pragma unroll
    for (int j = 0; j < 9; j++)
        s += g_spart[(size_t)(half*2 + hh + 4*j) * SND + base];
    s += __shfl_xor_sync(0xffffffffu, s, 16);
    if (lane < 16) red[pib][half][d] = s;
    __syncthreads();
    if (half == 0){
        float st = (red[pib][0][d] + red[pib][1][d]) * scale;
        float sq = st * st;
        sq += __shfl_xor_sync(0xffffffffu, sq, 1);
        sq += __shfl_xor_sync(0xffffffffu, sq, 2);
        sq += __shfl_xor_sync(0xffffffffu, sq, 4);
        sq += __shfl_xor_sync(0xffffffffu, sq, 8);
        float nrm = sqrtf(sq);
        float vv = (sq / (1.0f + sq)) * (st / (nrm + 1e-8f));
        if (lane < 16){
            if (MODE == 0)      g_vc[base] = vv;
            else if (MODE == 1) g_vc[base] += vv;
            else                out[base] = vv;
        }
    }
}

// ---------------- launch ----------------
extern "C" void kernel_launch(void* const* d_in, const int* in_sizes, int n_in,
                              void* d_out, int out_size){
    const float* x = (const float*)d_in[0];
    const float* W = (const float*)d_in[1];
    if (n_in >= 2 && in_sizes[0] == WELEMS){   // defensive order swap
        const float* t = x; x = W; W = t;
    }
    float* out = (float*)d_out;

    k_prep<<<XBLKS + WBLKS, 1024>>>(x, W);

    dim3 pg(CHUNKS, BGROUPS);
    const int RB = (B_TOT*NCAPS)/4;    // 640 blocks

    k_pass<0><<<pg, 320>>>();
    k_reduce<0><<<RB, 256>>>(nullptr, 0.1f);   // c = softmax(0) = 1/10

    k_pass<1><<<pg, 320>>>();
    k_reduce<1><<<RB, 256>>>(nullptr, 1.0f);

    k_pass<1><<<pg, 320>>>();
    k_reduce<1><<<RB, 256>>>(nullptr, 1.0f);

    k_pass<1><<<pg, 320>>>();
    k_reduce<2><<<RB, 256>>>(out, 1.0f);
}